// round 1
// baseline (speedup 1.0000x reference)
#include <cuda_runtime.h>

// CEHawkesProcess — Hawkes NLL.
// Inputs (metadata order):
// 0 event_times f32[B*L], 1 event_types i32[B*L], 2 event_categories i32[B*L],
// 3 T (scalar), 4 type_emb f32[NT*E], 5 cat_emb f32[NC*E], 6 a f32[NT*E],
// 7 b f32[NC*E], 8 A f32[NT*NT*E], 9 P f32[NT*NT*E], 10 Bm f32[NC*NC*E],
// 11 Q f32[NC*NC*E].  Output: scalar f32.

namespace {
constexpr int NTY = 50;
constexpr int NCA = 20;
constexpr int EMB = 64;
constexpr int BSZ = 4;
constexpr int SEQ = 256;
}

// Precomputed tables (scratch via __device__ globals — no allocations allowed).
// g_TT[(k*NTY+t)*EMB+e] = { f[t,e]*A[k,t,e]*f[k,e],  -log2(e)*f[t,e]*P[k,t,e]*f[k,e] }
__device__ float2 g_TT[NTY * NTY * EMB];
// g_TC[(c1*NCA+c2)*EMB+e] = { g[c2,e]*Bm[c1,c2,e]*g[c1,e], -log2(e)*g[c2,e]*Q[c1,c2,e]*g[c1,e] }
__device__ float2 g_TC[NCA * NCA * EMB];
__device__ float g_BA[NTY];        // sum_e f[t,e]*a[t,e]
__device__ float g_SP[NTY];        // sum_e softplus(f[t,e]*a[t,e])
__device__ float g_FB[NTY * NCA];  // sum_e f[t,e]*b[c,e]
__device__ float g_Fsum[EMB];      // sum_t f[t,e]
__device__ float g_I0;             // sum_t g_SP[t]
__device__ float g_Sba;            // sum_t g_BA[t]
__device__ float g_SFB[NCA];       // sum_t g_FB[t,c]
__device__ double g_ll;            // sum of event log-lik terms
__device__ double g_int;           // sum of history-dependent integral terms

__device__ __forceinline__ float fast_exp2(float x) {
    float r;
    asm("ex2.approx.ftz.f32 %0, %1;" : "=f"(r) : "f"(x));
    return r;
}

// T may arrive as int32 (value 128) or float32 bits; disambiguate.
__device__ __forceinline__ float readT(const void* p) {
    int v = *(const int*)p;
    return (v > 0 && v < (1 << 24)) ? (float)v : __int_as_float(v);
}

__device__ __forceinline__ float block_reduce_256(float v, float* sred) {
    #pragma unroll
    for (int o = 16; o; o >>= 1) v += __shfl_down_sync(0xffffffffu, v, o);
    int tid = threadIdx.x;
    if ((tid & 31) == 0) sred[tid >> 5] = v;
    __syncthreads();
    float r = 0.f;
    if (tid == 0) {
        #pragma unroll
        for (int w = 0; w < 8; w++) r += sred[w];
    }
    return r;
}

__global__ void k_tab_type(const float* __restrict__ f,
                           const float* __restrict__ A,
                           const float* __restrict__ P) {
    int kt = blockIdx.x;          // k*NTY + t
    int e = threadIdx.x;
    int k = kt / NTY, t = kt % NTY;
    float ft = f[t * EMB + e];
    float fk = f[k * EMB + e];
    float2 v;
    v.x = ft * A[kt * EMB + e] * fk;
    v.y = -1.4426950408889634f * ft * P[kt * EMB + e] * fk;
    g_TT[kt * EMB + e] = v;
}

__global__ void k_tab_cat(const float* __restrict__ g,
                          const float* __restrict__ Bm,
                          const float* __restrict__ Q) {
    int cc = blockIdx.x;          // c1*NCA + c2
    int e = threadIdx.x;
    int c1 = cc / NCA, c2 = cc % NCA;
    float gc2 = g[c2 * EMB + e];
    float gc1 = g[c1 * EMB + e];
    float2 v;
    v.x = gc2 * Bm[cc * EMB + e] * gc1;
    v.y = -1.4426950408889634f * gc2 * Q[cc * EMB + e] * gc1;
    g_TC[cc * EMB + e] = v;
}

__global__ void k_prep(const float* __restrict__ f,
                       const float* __restrict__ g,
                       const float* __restrict__ a,
                       const float* __restrict__ b) {
    int tid = threadIdx.x;
    if (tid == 0) { g_ll = 0.0; g_int = 0.0; }
    if (tid < NTY) {
        float ba = 0.f, sp = 0.f;
        for (int e = 0; e < EMB; e++) {
            float x = f[tid * EMB + e] * a[tid * EMB + e];
            ba += x;
            sp += fmaxf(x, 0.f) + log1pf(expf(-fabsf(x)));
        }
        g_BA[tid] = ba;
        g_SP[tid] = sp;
    }
    for (int idx = tid; idx < NTY * NCA; idx += blockDim.x) {
        int t = idx / NCA, c = idx % NCA;
        float s = 0.f;
        for (int e = 0; e < EMB; e++) s += f[t * EMB + e] * b[c * EMB + e];
        g_FB[idx] = s;
    }
    if (tid < EMB) {
        float s = 0.f;
        for (int t = 0; t < NTY; t++) s += f[t * EMB + tid];
        g_Fsum[tid] = s;
    }
    __syncthreads();
    if (tid == 0) {
        float s = 0.f, i0 = 0.f;
        for (int t = 0; t < NTY; t++) { s += g_BA[t]; i0 += g_SP[t]; }
        g_Sba = s;
        g_I0 = i0;
    }
    if (tid < NCA) {
        float s = 0.f;
        for (int t = 0; t < NTY; t++) s += g_FB[t * NCA + tid];
        g_SFB[tid] = s;
    }
}

// One block per event (b,i). 256 threads: e = tid&63, 4 history lanes.
__global__ void __launch_bounds__(256) k_events(const float* __restrict__ times,
                                                const int* __restrict__ types,
                                                const int* __restrict__ cats,
                                                const float* __restrict__ f) {
    int b = blockIdx.x / SEQ;
    int i = blockIdx.x % SEQ;
    const float* ts = times + b * SEQ;
    const int* ty = types + b * SEQ;
    const int* ct = cats + b * SEQ;
    int tid = threadIdx.x;

    int ti = ty[i];
    float t_i = ts[i];

    if (i == 0) {
        if (tid == 0 && t_i >= 0.f) {
            float lam = g_SP[ti];
            atomicAdd(&g_ll, (double)(logf(lam + 1e-16f) + lam));
        }
        return;
    }

    __shared__ float sh_t[SEQ];
    __shared__ int sh_k[SEQ];
    __shared__ int sh_c[SEQ];
    __shared__ float sred[8];
    for (int s = tid; s < i; s += blockDim.x) {
        sh_t[s] = ts[s];
        sh_k[s] = ty[s];
        sh_c[s] = ct[s];
    }
    __syncthreads();

    int lc = ct[i - 1];
    int e = tid & (EMB - 1);
    int ch = tid >> 6;  // 0..3

    const float2* __restrict__ ttb = g_TT + ti * EMB + e;   // index by k: + k*NTY*EMB
    const float2* __restrict__ tcb = g_TC + lc * EMB + e;   // index by c: + c*NCA*EMB
    float accT = 0.f, accC = 0.f;
    for (int s = ch; s < i; s += 4) {
        float td = t_i - sh_t[s];
        float2 wt = ttb[sh_k[s] * (NTY * EMB)];
        float2 wc = tcb[sh_c[s] * (NCA * EMB)];
        accT += wt.x * fast_exp2(wt.y * td);
        accC += wc.x * fast_exp2(wc.y * td);
    }
    float fe = f[ti * EMB + e];
    float acc = fmaf(fe, accC, accT);

    float total = block_reduce_256(acc, sred);
    if (tid == 0 && t_i >= 0.f) {
        float lam = g_BA[ti] + g_FB[ti * NCA + lc] + total;
        atomicAdd(&g_ll, (double)(logf(lam + 1e-16f) + lam));
    }
}

// Horizon type channel: one block per (b, t) — sum_e m_T[t,e], scaled by (T - t_last).
__global__ void __launch_bounds__(256) k_horT(const float* __restrict__ times,
                                              const int* __restrict__ types,
                                              const void* __restrict__ Tp) {
    int b = blockIdx.x / NTY;
    int t = blockIdx.x % NTY;
    float Tf = readT(Tp);
    const float* ts = times + b * SEQ;
    const int* ty = types + b * SEQ;
    int tid = threadIdx.x;

    __shared__ float sh_t[SEQ];
    __shared__ int sh_k[SEQ];
    __shared__ float sred[8];
    for (int s = tid; s < SEQ; s += blockDim.x) {
        sh_t[s] = ts[s];
        sh_k[s] = ty[s];
    }
    __syncthreads();

    int e = tid & (EMB - 1);
    int ch = tid >> 6;
    const float2* __restrict__ ttb = g_TT + t * EMB + e;
    float acc = 0.f;
    for (int s = ch; s < SEQ; s += 4) {
        float td = Tf - sh_t[s];
        float2 wt = ttb[sh_k[s] * (NTY * EMB)];
        acc += wt.x * fast_exp2(wt.y * td);
    }
    float total = block_reduce_256(acc, sred);
    if (tid == 0) {
        float tlast = sh_t[SEQ - 1];
        atomicAdd(&g_int, (double)(total * (Tf - tlast)));
    }
}

// Horizon cat channel: one block per b — sum_e Fsum[e]*n_T[lcL,e], scaled by (T - t_last).
__global__ void __launch_bounds__(256) k_horC(const float* __restrict__ times,
                                              const int* __restrict__ cats,
                                              const void* __restrict__ Tp) {
    int b = blockIdx.x;
    float Tf = readT(Tp);
    const float* ts = times + b * SEQ;
    const int* ct = cats + b * SEQ;
    int tid = threadIdx.x;

    __shared__ float sh_t[SEQ];
    __shared__ int sh_c[SEQ];
    __shared__ float sred[8];
    for (int s = tid; s < SEQ; s += blockDim.x) {
        sh_t[s] = ts[s];
        sh_c[s] = ct[s];
    }
    __syncthreads();

    int lcL = ct[SEQ - 1];
    int e = tid & (EMB - 1);
    int ch = tid >> 6;
    const float2* __restrict__ tcb = g_TC + lcL * EMB + e;
    float fs = g_Fsum[e];
    float acc = 0.f;
    for (int s = ch; s < SEQ; s += 4) {
        float td = Tf - sh_t[s];
        float2 wc = tcb[sh_c[s] * (NCA * EMB)];
        acc += wc.x * fast_exp2(wc.y * td);
    }
    acc *= fs;
    float total = block_reduce_256(acc, sred);
    if (tid == 0) {
        float tlast = sh_t[SEQ - 1];
        atomicAdd(&g_int, (double)(total * (Tf - tlast)));
    }
}

__global__ void k_final(const float* __restrict__ times,
                        const int* __restrict__ cats,
                        const void* __restrict__ Tp,
                        float* __restrict__ out) {
    float Tf = readT(Tp);
    double extra = 0.0;
    for (int b = 0; b < BSZ; b++) {
        int lcL = cats[b * SEQ + SEQ - 1];
        float tlast = times[b * SEQ + SEQ - 1];
        float t0 = times[b * SEQ];
        extra += (double)((g_Sba + g_SFB[lcL]) * (Tf - tlast) + g_I0 * t0);
    }
    out[0] = (float)(-(g_ll - (g_int + extra)));
}

extern "C" void kernel_launch(void* const* d_in, const int* in_sizes, int n_in,
                              void* d_out, int out_size) {
    const float* times = (const float*)d_in[0];
    const int* types = (const int*)d_in[1];
    const int* cats = (const int*)d_in[2];
    const void* Tp = d_in[3];
    const float* type_emb = (const float*)d_in[4];
    const float* cat_emb = (const float*)d_in[5];
    const float* a = (const float*)d_in[6];
    const float* b = (const float*)d_in[7];
    const float* A = (const float*)d_in[8];
    const float* P = (const float*)d_in[9];
    const float* Bm = (const float*)d_in[10];
    const float* Q = (const float*)d_in[11];
    float* out = (float*)d_out;

    k_tab_type<<<NTY * NTY, EMB>>>(type_emb, A, P);
    k_tab_cat<<<NCA * NCA, EMB>>>(cat_emb, Bm, Q);
    k_prep<<<1, 256>>>(type_emb, cat_emb, a, b);
    k_events<<<BSZ * SEQ, 256>>>(times, types, cats, type_emb);
    k_horT<<<BSZ * NTY, 256>>>(times, types, Tp);
    k_horC<<<BSZ, 256>>>(times, cats, Tp);
    k_final<<<1, 1>>>(times, cats, Tp, out);
}

// round 2
// speedup vs baseline: 1.2407x; 1.2407x over previous
#include <cuda_runtime.h>

// CEHawkesProcess — Hawkes NLL. Fused: 2 launches total.
// Inputs (metadata order):
// 0 event_times f32[B*L], 1 event_types i32[B*L], 2 event_categories i32[B*L],
// 3 T (scalar), 4 type_emb f32[NT*E], 5 cat_emb f32[NC*E], 6 a f32[NT*E],
// 7 b f32[NC*E], 8 A f32[NT*NT*E], 9 P f32[NT*NT*E], 10 Bm f32[NC*NC*E],
// 11 Q f32[NC*NC*E].  Output: scalar f32.

namespace {
constexpr int NTY = 50;
constexpr int NCA = 20;
constexpr int EMB = 64;
constexpr int BSZ = 4;
constexpr int SEQ = 256;

constexpr int TT_BLKS = (NTY * NTY) / 4;       // 625  (4 rows of 64 per block)
constexpr int TC_BLKS = (NCA * NCA) / 4;       // 100
constexpr int PREP_BLKS = TT_BLKS + TC_BLKS + 1;  // 726

constexpr int EV_BLKS = BSZ * SEQ;             // 1024
constexpr int HT_BLKS = BSZ * NTY;             // 200
constexpr int HC_BLKS = BSZ;                   // 4
constexpr int MAIN_BLKS = EV_BLKS + HT_BLKS + HC_BLKS;  // 1228
}

// Precomputed tables (scratch via __device__ globals — no allocations allowed).
// g_TT[(k*NTY+t)*EMB+e] = { f[t,e]*A[k,t,e]*f[k,e],  -log2(e)*f[t,e]*P[k,t,e]*f[k,e] }
__device__ float2 g_TT[NTY * NTY * EMB];
__device__ float2 g_TC[NCA * NCA * EMB];
__device__ float g_BA[NTY];        // sum_e f[t,e]*a[t,e]
__device__ float g_SP[NTY];        // sum_e softplus(f[t,e]*a[t,e])
__device__ float g_FB[NTY * NCA];  // sum_e f[t,e]*b[c,e]
__device__ float g_Fsum[EMB];      // sum_t f[t,e]
__device__ float g_I0;
__device__ float g_Sba;
__device__ float g_SFB[NCA];
__device__ double g_ll;
__device__ double g_int;
__device__ unsigned g_done;

__device__ __forceinline__ float fast_exp2(float x) {
    float r;
    asm("ex2.approx.ftz.f32 %0, %1;" : "=f"(r) : "f"(x));
    return r;
}

// T may arrive as int32 (value 128) or float32 bits; disambiguate.
__device__ __forceinline__ float readT(const void* p) {
    int v = *(const int*)p;
    return (v > 0 && v < (1 << 24)) ? (float)v : __int_as_float(v);
}

__device__ __forceinline__ float block_reduce_256(float v, float* sred) {
    #pragma unroll
    for (int o = 16; o; o >>= 1) v += __shfl_down_sync(0xffffffffu, v, o);
    int tid = threadIdx.x;
    if ((tid & 31) == 0) sred[tid >> 5] = v;
    __syncthreads();
    float r = 0.f;
    if (tid == 0) {
        #pragma unroll
        for (int w = 0; w < 8; w++) r += sred[w];
    }
    return r;
}

// ---------------- Fused prep: tables + scalar precomputes + resets ----------
__global__ void __launch_bounds__(256) k_prep_all(
    const float* __restrict__ f, const float* __restrict__ g,
    const float* __restrict__ a, const float* __restrict__ b,
    const float* __restrict__ A, const float* __restrict__ P,
    const float* __restrict__ Bm, const float* __restrict__ Q) {
    int bid = blockIdx.x;
    int tid = threadIdx.x;
    if (bid < TT_BLKS) {
        int kt = bid * 4 + (tid >> 6);         // k*NTY + t
        int e = tid & (EMB - 1);
        int k = kt / NTY, t = kt - k * NTY;
        float ft = f[t * EMB + e];
        float fk = f[k * EMB + e];
        float2 v;
        v.x = ft * A[kt * EMB + e] * fk;
        v.y = -1.4426950408889634f * ft * P[kt * EMB + e] * fk;
        g_TT[kt * EMB + e] = v;
        return;
    }
    if (bid < TT_BLKS + TC_BLKS) {
        int cc = (bid - TT_BLKS) * 4 + (tid >> 6);  // c1*NCA + c2
        int e = tid & (EMB - 1);
        int c1 = cc / NCA, c2 = cc - c1 * NCA;
        float g2 = g[c2 * EMB + e];
        float g1 = g[c1 * EMB + e];
        float2 v;
        v.x = g2 * Bm[cc * EMB + e] * g1;
        v.y = -1.4426950408889634f * g2 * Q[cc * EMB + e] * g1;
        g_TC[cc * EMB + e] = v;
        return;
    }
    // scalar precompute block
    if (tid == 0) { g_ll = 0.0; g_int = 0.0; g_done = 0u; }
    if (tid < NTY) {
        float ba = 0.f, sp = 0.f;
        for (int e = 0; e < EMB; e++) {
            float x = f[tid * EMB + e] * a[tid * EMB + e];
            ba += x;
            sp += fmaxf(x, 0.f) + log1pf(expf(-fabsf(x)));
        }
        g_BA[tid] = ba;
        g_SP[tid] = sp;
    }
    for (int idx = tid; idx < NTY * NCA; idx += blockDim.x) {
        int t = idx / NCA, c = idx - t * NCA;
        float s = 0.f;
        for (int e = 0; e < EMB; e++) s += f[t * EMB + e] * b[c * EMB + e];
        g_FB[idx] = s;
    }
    if (tid < EMB) {
        float s = 0.f;
        for (int t = 0; t < NTY; t++) s += f[t * EMB + tid];
        g_Fsum[tid] = s;
    }
    __syncthreads();
    if (tid == 0) {
        float s = 0.f, i0 = 0.f;
        for (int t = 0; t < NTY; t++) { s += g_BA[t]; i0 += g_SP[t]; }
        g_Sba = s;
        g_I0 = i0;
    }
    if (tid < NCA) {
        float s = 0.f;
        for (int t = 0; t < NTY; t++) s += g_FB[t * NCA + tid];
        g_SFB[tid] = s;
    }
}

// ---------------- Fused main: events + horizon + finalizer ------------------
struct alignas(16) Ent { float t; int ko; int co; int pad; };

__global__ void __launch_bounds__(256) k_main(
    const float* __restrict__ times, const int* __restrict__ types,
    const int* __restrict__ cats, const void* __restrict__ Tp,
    const float* __restrict__ f, float* __restrict__ out) {
    int bid = blockIdx.x;
    int tid = threadIdx.x;
    __shared__ Ent sh[SEQ];
    __shared__ float sred[8];

    if (bid < EV_BLKS) {
        // ---- per-event log-likelihood ----
        int b = bid >> 8;
        int i = bid & (SEQ - 1);
        const float* ts = times + b * SEQ;
        const int* ty = types + b * SEQ;
        const int* ct = cats + b * SEQ;
        int ti = ty[i];
        float t_i = ts[i];

        if (i == 0) {
            if (tid == 0 && t_i >= 0.f) {
                float lam = g_SP[ti];
                atomicAdd(&g_ll, (double)(logf(lam + 1e-16f) + lam));
            }
        } else {
            for (int s = tid; s < i; s += blockDim.x) {
                Ent en;
                en.t = ts[s];
                en.ko = ty[s] * (NTY * EMB);
                en.co = ct[s] * (NCA * EMB);
                en.pad = 0;
                sh[s] = en;
            }
            __syncthreads();

            int lc = ct[i - 1];
            int e = tid & (EMB - 1);
            int ch = tid >> 6;  // 0..3

            const float2* __restrict__ ttb = g_TT + ti * EMB + e;
            const float2* __restrict__ tcb = g_TC + lc * EMB + e;
            float aT0 = 0.f, aT1 = 0.f, aC0 = 0.f, aC1 = 0.f;
            int s = ch;
            for (; s + 4 < i; s += 8) {
                Ent e0 = sh[s];
                Ent e1 = sh[s + 4];
                float td0 = t_i - e0.t;
                float td1 = t_i - e1.t;
                float2 wt0 = __ldg(ttb + e0.ko);
                float2 wc0 = __ldg(tcb + e0.co);
                float2 wt1 = __ldg(ttb + e1.ko);
                float2 wc1 = __ldg(tcb + e1.co);
                aT0 = fmaf(wt0.x, fast_exp2(wt0.y * td0), aT0);
                aC0 = fmaf(wc0.x, fast_exp2(wc0.y * td0), aC0);
                aT1 = fmaf(wt1.x, fast_exp2(wt1.y * td1), aT1);
                aC1 = fmaf(wc1.x, fast_exp2(wc1.y * td1), aC1);
            }
            if (s < i) {
                Ent e0 = sh[s];
                float td0 = t_i - e0.t;
                float2 wt0 = __ldg(ttb + e0.ko);
                float2 wc0 = __ldg(tcb + e0.co);
                aT0 = fmaf(wt0.x, fast_exp2(wt0.y * td0), aT0);
                aC0 = fmaf(wc0.x, fast_exp2(wc0.y * td0), aC0);
            }
            float fe = f[ti * EMB + e];
            float acc = (aT0 + aT1) + fe * (aC0 + aC1);

            float total = block_reduce_256(acc, sred);
            if (tid == 0 && t_i >= 0.f) {
                float lam = g_BA[ti] + g_FB[ti * NCA + lc] + total;
                atomicAdd(&g_ll, (double)(logf(lam + 1e-16f) + lam));
            }
        }
    } else if (bid < EV_BLKS + HT_BLKS) {
        // ---- horizon type channel: (b, t) ----
        int idx = bid - EV_BLKS;
        int b = idx / NTY;
        int t = idx - b * NTY;
        float Tf = readT(Tp);
        const float* ts = times + b * SEQ;
        const int* ty = types + b * SEQ;
        for (int s = tid; s < SEQ; s += blockDim.x) {
            Ent en;
            en.t = ts[s];
            en.ko = ty[s] * (NTY * EMB);
            en.co = 0;
            en.pad = 0;
            sh[s] = en;
        }
        __syncthreads();
        int e = tid & (EMB - 1);
        int ch = tid >> 6;
        const float2* __restrict__ ttb = g_TT + t * EMB + e;
        float a0 = 0.f, a1 = 0.f;
        #pragma unroll 4
        for (int s = ch; s < SEQ; s += 8) {
            Ent e0 = sh[s];
            Ent e1 = sh[s + 4];
            float2 wt0 = __ldg(ttb + e0.ko);
            float2 wt1 = __ldg(ttb + e1.ko);
            a0 = fmaf(wt0.x, fast_exp2(wt0.y * (Tf - e0.t)), a0);
            a1 = fmaf(wt1.x, fast_exp2(wt1.y * (Tf - e1.t)), a1);
        }
        float total = block_reduce_256(a0 + a1, sred);
        if (tid == 0) {
            float tlast = ts[SEQ - 1];
            atomicAdd(&g_int, (double)(total * (Tf - tlast)));
        }
    } else {
        // ---- horizon cat channel: b ----
        int b = bid - EV_BLKS - HT_BLKS;
        float Tf = readT(Tp);
        const float* ts = times + b * SEQ;
        const int* ct = cats + b * SEQ;
        for (int s = tid; s < SEQ; s += blockDim.x) {
            Ent en;
            en.t = ts[s];
            en.co = ct[s] * (NCA * EMB);
            en.ko = 0;
            en.pad = 0;
            sh[s] = en;
        }
        __syncthreads();
        int lcL = ct[SEQ - 1];
        int e = tid & (EMB - 1);
        int ch = tid >> 6;
        const float2* __restrict__ tcb = g_TC + lcL * EMB + e;
        float fs = g_Fsum[e];
        float a0 = 0.f, a1 = 0.f;
        #pragma unroll 4
        for (int s = ch; s < SEQ; s += 8) {
            Ent e0 = sh[s];
            Ent e1 = sh[s + 4];
            float2 wc0 = __ldg(tcb + e0.co);
            float2 wc1 = __ldg(tcb + e1.co);
            a0 = fmaf(wc0.x, fast_exp2(wc0.y * (Tf - e0.t)), a0);
            a1 = fmaf(wc1.x, fast_exp2(wc1.y * (Tf - e1.t)), a1);
        }
        float total = block_reduce_256((a0 + a1) * fs, sred);
        if (tid == 0) {
            float tlast = ts[SEQ - 1];
            atomicAdd(&g_int, (double)(total * (Tf - tlast)));
        }
    }

    // ---- grid-completion finalizer ----
    __syncthreads();
    if (tid == 0) {
        __threadfence();
        unsigned n = atomicAdd(&g_done, 1u);
        if (n == (unsigned)(MAIN_BLKS - 1)) {
            __threadfence();
            float Tf = readT(Tp);
            double extra = 0.0;
            for (int b = 0; b < BSZ; b++) {
                int lcL = cats[b * SEQ + SEQ - 1];
                float tlast = times[b * SEQ + SEQ - 1];
                float t0 = times[b * SEQ];
                extra += (double)((g_Sba + g_SFB[lcL]) * (Tf - tlast) + g_I0 * t0);
            }
            out[0] = (float)(-(g_ll - (g_int + extra)));
        }
    }
}

extern "C" void kernel_launch(void* const* d_in, const int* in_sizes, int n_in,
                              void* d_out, int out_size) {
    const float* times = (const float*)d_in[0];
    const int* types = (const int*)d_in[1];
    const int* cats = (const int*)d_in[2];
    const void* Tp = d_in[3];
    const float* type_emb = (const float*)d_in[4];
    const float* cat_emb = (const float*)d_in[5];
    const float* a = (const float*)d_in[6];
    const float* b = (const float*)d_in[7];
    const float* A = (const float*)d_in[8];
    const float* P = (const float*)d_in[9];
    const float* Bm = (const float*)d_in[10];
    const float* Q = (const float*)d_in[11];
    float* out = (float*)d_out;

    k_prep_all<<<PREP_BLKS, 256>>>(type_emb, cat_emb, a, b, A, P, Bm, Q);
    k_main<<<MAIN_BLKS, 256>>>(times, types, cats, Tp, type_emb, out);
}

// round 3
// speedup vs baseline: 1.8092x; 1.4581x over previous
#include <cuda_runtime.h>

// CEHawkesProcess — Hawkes NLL. Single fused launch; no precomputed tables.
// Inputs (metadata order):
// 0 event_times f32[B*L], 1 event_types i32[B*L], 2 event_categories i32[B*L],
// 3 T (scalar), 4 type_emb f32[NT*E], 5 cat_emb f32[NC*E], 6 a f32[NT*E],
// 7 b f32[NC*E], 8 A f32[NT*NT*E], 9 P f32[NT*NT*E], 10 Bm f32[NC*NC*E],
// 11 Q f32[NC*NC*E].  Output: scalar f32.

namespace {
constexpr int NTY = 50;
constexpr int NCA = 20;
constexpr int EMB = 64;
constexpr int BSZ = 4;
constexpr int SEQ = 256;

constexpr int HC_BLKS = BSZ;                              // 4   (heaviest first)
constexpr int HT_BLKS = BSZ * NTY;                        // 200
constexpr int EV_BLKS = BSZ * SEQ;                        // 1024
constexpr int MAIN_BLKS = HC_BLKS + HT_BLKS + EV_BLKS;    // 1228
constexpr float NL2E = -1.4426950408889634f;              // -log2(e)
}

// Per-block partial results + completion counter (zero-init; finalizer resets).
__device__ float g_part[MAIN_BLKS];
__device__ unsigned g_done;

struct alignas(16) Ent { float t; int koA; int coB; int kfgf; };

__device__ __forceinline__ float fast_exp2(float x) {
    float r;
    asm("ex2.approx.ftz.f32 %0, %1;" : "=f"(r) : "f"(x));
    return r;
}

// T may arrive as int32 (value 128) or float32 bits; disambiguate.
__device__ __forceinline__ float readT(const void* p) {
    int v = *(const int*)p;
    return (v > 0 && v < (1 << 24)) ? (float)v : __int_as_float(v);
}

__device__ __forceinline__ float softplusf(float x) {
    return fmaxf(x, 0.f) + log1pf(expf(-fabsf(x)));
}

__device__ __forceinline__ float block_reduce_256(float v, float* sred) {
    #pragma unroll
    for (int o = 16; o; o >>= 1) v += __shfl_down_sync(0xffffffffu, v, o);
    int tid = threadIdx.x;
    if ((tid & 31) == 0) sred[tid >> 5] = v;
    __syncthreads();
    float r = 0.f;
    if (tid == 0) {
        #pragma unroll
        for (int w = 0; w < 8; w++) r += sred[w];
    }
    return r;
}

__global__ void __launch_bounds__(256) k_all(
    const float* __restrict__ times, const int* __restrict__ types,
    const int* __restrict__ cats, const void* __restrict__ Tp,
    const float* __restrict__ f, const float* __restrict__ g,
    const float* __restrict__ a, const float* __restrict__ b,
    const float* __restrict__ A, const float* __restrict__ P,
    const float* __restrict__ Bm, const float* __restrict__ Q,
    float* __restrict__ out) {
    int bid = blockIdx.x;
    int tid = threadIdx.x;

    __shared__ float f_sh[NTY * EMB];   // 12.8 KB
    __shared__ float g_sh[NCA * EMB];   // 5 KB
    __shared__ Ent sh[SEQ];             // 4 KB
    __shared__ float sred[8];
    __shared__ double dred[8];
    __shared__ int sh_last;

    // Embedding tables into shared (used by every path).
    for (int idx = tid; idx < NTY * EMB; idx += 256) f_sh[idx] = f[idx];
    for (int idx = tid; idx < NCA * EMB; idx += 256) g_sh[idx] = g[idx];

    int e = tid & (EMB - 1);
    int ch = tid >> 6;  // 0..3
    float partial = 0.f;

    if (bid < HC_BLKS) {
        // ======== horizon category channel + base/softplus scalars, per seq ====
        int bb = bid;
        float Tf = readT(Tp);
        const float* ts = times + bb * SEQ;
        const int* ct = cats + bb * SEQ;
        for (int s = tid; s < SEQ; s += 256) {
            Ent en;
            en.t = ts[s];
            int c = ct[s];
            en.coB = c * (NCA * EMB);
            en.koA = 0;
            en.kfgf = (c * EMB) << 16;
            sh[s] = en;
        }
        __syncthreads();

        int lcL = sh[SEQ - 1].kfgf >> 16;  // c*EMB of last event
        lcL /= EMB;
        float tlast = sh[SEQ - 1].t;
        float t0 = sh[0].t;
        float ge = g_sh[lcL * EMB + e];
        float cC = NL2E * ge;
        const float* Bbase = Bm + lcL * EMB + e;
        const float* Qbase = Q + lcL * EMB + e;

        float a0 = 0.f, a1 = 0.f;
        #pragma unroll 4
        for (int s = ch; s < SEQ; s += 8) {
            Ent e0 = sh[s];
            Ent e1 = sh[s + 4];
            float gk0 = g_sh[(e0.kfgf >> 16) + e];
            float gk1 = g_sh[(e1.kfgf >> 16) + e];
            float Bv0 = __ldg(Bbase + e0.coB);
            float Qv0 = __ldg(Qbase + e0.coB);
            float Bv1 = __ldg(Bbase + e1.coB);
            float Qv1 = __ldg(Qbase + e1.coB);
            float td0 = Tf - e0.t;
            float td1 = Tf - e1.t;
            a0 = fmaf(gk0 * Bv0, fast_exp2(gk0 * td0 * Qv0 * cC), a0);
            a1 = fmaf(gk1 * Bv1, fast_exp2(gk1 * td1 * Qv1 * cC), a1);
        }
        float Fsum_e = 0.f;
        #pragma unroll
        for (int t = 0; t < NTY; t++) Fsum_e += f_sh[t * EMB + e];
        float decay_term = Fsum_e * ge * (a0 + a1);

        // Sba = sum f*a; I0 = sum softplus(f*a); SFB = sum_t f[t,e]*b[lcL,e]
        float sba = 0.f, i0 = 0.f, sfb = 0.f;
        for (int idx = tid; idx < NTY * EMB; idx += 256) {
            float fv = f_sh[idx];
            float x = fv * __ldg(a + idx);
            sba += x;
            i0 += softplusf(x);
            sfb += fv * __ldg(b + lcL * EMB + (idx & (EMB - 1)));
        }
        float val = (decay_term + sba + sfb) * (Tf - tlast) + i0 * t0;
        partial = block_reduce_256(val, sred);           // + integral
    } else if (bid < HC_BLKS + HT_BLKS) {
        // ======== horizon type channel: (b, t) =================================
        int idx0 = bid - HC_BLKS;
        int bb = idx0 / NTY;
        int t = idx0 - bb * NTY;
        float Tf = readT(Tp);
        const float* ts = times + bb * SEQ;
        const int* ty = types + bb * SEQ;
        for (int s = tid; s < SEQ; s += 256) {
            Ent en;
            en.t = ts[s];
            int k = ty[s];
            en.koA = k * (NTY * EMB);
            en.coB = 0;
            en.kfgf = k * EMB;
            sh[s] = en;
        }
        __syncthreads();

        float tlast = sh[SEQ - 1].t;
        float fe = f_sh[t * EMB + e];
        float cT = NL2E * fe;
        const float* Abase = A + t * EMB + e;
        const float* Pbase = P + t * EMB + e;
        float a0 = 0.f, a1 = 0.f;
        #pragma unroll 4
        for (int s = ch; s < SEQ; s += 8) {
            Ent e0 = sh[s];
            Ent e1 = sh[s + 4];
            float fk0 = f_sh[(e0.kfgf & 0xFFFF) + e];
            float fk1 = f_sh[(e1.kfgf & 0xFFFF) + e];
            float Av0 = __ldg(Abase + e0.koA);
            float Pv0 = __ldg(Pbase + e0.koA);
            float Av1 = __ldg(Abase + e1.koA);
            float Pv1 = __ldg(Pbase + e1.koA);
            float td0 = Tf - e0.t;
            float td1 = Tf - e1.t;
            a0 = fmaf(fk0 * Av0, fast_exp2(fk0 * td0 * Pv0 * cT), a0);
            a1 = fmaf(fk1 * Av1, fast_exp2(fk1 * td1 * Pv1 * cT), a1);
        }
        float val = fe * (a0 + a1);
        float total = block_reduce_256(val, sred);
        partial = total * (Tf - tlast);                  // + integral
    } else {
        // ======== per-event log-likelihood ======================================
        int local = bid - HC_BLKS - HT_BLKS;
        int bb = local >> 8;
        int i = (SEQ - 1) - (local & (SEQ - 1));         // big-i blocks first
        const float* ts = times + bb * SEQ;
        const int* ty = types + bb * SEQ;
        const int* ct = cats + bb * SEQ;
        int ti = ty[i];
        float t_i = ts[i];

        if (i == 0) {
            __syncthreads();
            float v = 0.f;
            if (tid < EMB) v = softplusf(f_sh[ti * EMB + tid] * __ldg(a + ti * EMB + tid));
            float lam = block_reduce_256(v, sred);
            if (tid == 0 && t_i >= 0.f) partial = -(logf(lam + 1e-16f) + lam);
        } else {
            for (int s = tid; s < i; s += 256) {
                Ent en;
                en.t = ts[s];
                int k = ty[s];
                int c = ct[s];
                en.koA = k * (NTY * EMB);
                en.coB = c * (NCA * EMB);
                en.kfgf = (k * EMB) | ((c * EMB) << 16);
                sh[s] = en;
            }
            __syncthreads();

            int lc = ct[i - 1];
            float fe = f_sh[ti * EMB + e];
            float ge = g_sh[lc * EMB + e];
            float cT = NL2E * fe;
            float cC = NL2E * ge;
            const float* Abase = A + ti * EMB + e;
            const float* Pbase = P + ti * EMB + e;
            const float* Bbase = Bm + lc * EMB + e;
            const float* Qbase = Q + lc * EMB + e;

            float aT0 = 0.f, aT1 = 0.f, aC0 = 0.f, aC1 = 0.f;
            int s = ch;
            for (; s + 4 < i; s += 8) {
                Ent e0 = sh[s];
                Ent e1 = sh[s + 4];
                float fk0 = f_sh[(e0.kfgf & 0xFFFF) + e];
                float gk0 = g_sh[(e0.kfgf >> 16) + e];
                float fk1 = f_sh[(e1.kfgf & 0xFFFF) + e];
                float gk1 = g_sh[(e1.kfgf >> 16) + e];
                float Av0 = __ldg(Abase + e0.koA);
                float Pv0 = __ldg(Pbase + e0.koA);
                float Bv0 = __ldg(Bbase + e0.coB);
                float Qv0 = __ldg(Qbase + e0.coB);
                float Av1 = __ldg(Abase + e1.koA);
                float Pv1 = __ldg(Pbase + e1.koA);
                float Bv1 = __ldg(Bbase + e1.coB);
                float Qv1 = __ldg(Qbase + e1.coB);
                float td0 = t_i - e0.t;
                float td1 = t_i - e1.t;
                aT0 = fmaf(fk0 * Av0, fast_exp2(fk0 * td0 * Pv0 * cT), aT0);
                aC0 = fmaf(gk0 * Bv0, fast_exp2(gk0 * td0 * Qv0 * cC), aC0);
                aT1 = fmaf(fk1 * Av1, fast_exp2(fk1 * td1 * Pv1 * cT), aT1);
                aC1 = fmaf(gk1 * Bv1, fast_exp2(gk1 * td1 * Qv1 * cC), aC1);
            }
            if (s < i) {
                Ent e0 = sh[s];
                float fk0 = f_sh[(e0.kfgf & 0xFFFF) + e];
                float gk0 = g_sh[(e0.kfgf >> 16) + e];
                float Av0 = __ldg(Abase + e0.koA);
                float Pv0 = __ldg(Pbase + e0.koA);
                float Bv0 = __ldg(Bbase + e0.coB);
                float Qv0 = __ldg(Qbase + e0.coB);
                float td0 = t_i - e0.t;
                aT0 = fmaf(fk0 * Av0, fast_exp2(fk0 * td0 * Pv0 * cT), aT0);
                aC0 = fmaf(gk0 * Bv0, fast_exp2(gk0 * td0 * Qv0 * cC), aC0);
            }
            float acc = fe * (fmaf(ge, aC0 + aC1, aT0 + aT1));
            if (ch == 0)
                acc += fe * (__ldg(a + ti * EMB + e) + __ldg(b + lc * EMB + e));

            float lam = block_reduce_256(acc, sred);
            if (tid == 0 && t_i >= 0.f) partial = -(logf(lam + 1e-16f) + lam);
        }
    }

    // ======== publish partial + grid-completion finalizer ======================
    if (tid == 0) {
        g_part[bid] = partial;
        __threadfence();
        unsigned n = atomicAdd(&g_done, 1u);
        sh_last = (n == (unsigned)(MAIN_BLKS - 1)) ? 1 : 0;
        if (sh_last) __threadfence();
    }
    __syncthreads();
    if (sh_last) {
        double v = 0.0;
        for (int idx = tid; idx < MAIN_BLKS; idx += 256) v += (double)g_part[idx];
        #pragma unroll
        for (int o = 16; o; o >>= 1) v += __shfl_down_sync(0xffffffffu, v, o);
        if ((tid & 31) == 0) dred[tid >> 5] = v;
        __syncthreads();
        if (tid == 0) {
            double r = 0.0;
            #pragma unroll
            for (int w = 0; w < 8; w++) r += dred[w];
            out[0] = (float)r;
            g_done = 0u;   // reset for next replay
        }
    }
}

extern "C" void kernel_launch(void* const* d_in, const int* in_sizes, int n_in,
                              void* d_out, int out_size) {
    const float* times = (const float*)d_in[0];
    const int* types = (const int*)d_in[1];
    const int* cats = (const int*)d_in[2];
    const void* Tp = d_in[3];
    const float* type_emb = (const float*)d_in[4];
    const float* cat_emb = (const float*)d_in[5];
    const float* a = (const float*)d_in[6];
    const float* b = (const float*)d_in[7];
    const float* A = (const float*)d_in[8];
    const float* P = (const float*)d_in[9];
    const float* Bm = (const float*)d_in[10];
    const float* Q = (const float*)d_in[11];
    float* out = (float*)d_out;

    k_all<<<MAIN_BLKS, 256>>>(times, types, cats, Tp, type_emb, cat_emb,
                              a, b, A, P, Bm, Q, out);
}

// round 4
// speedup vs baseline: 2.5379x; 1.4028x over previous
#include <cuda_runtime.h>

// CEHawkesProcess — Hawkes NLL. 2 launches: parallel prep (tables+scalars) + fused main.
// Inputs (metadata order):
// 0 event_times f32[B*L], 1 event_types i32[B*L], 2 event_categories i32[B*L],
// 3 T (scalar), 4 type_emb f32[NT*E], 5 cat_emb f32[NC*E], 6 a f32[NT*E],
// 7 b f32[NC*E], 8 A f32[NT*NT*E], 9 P f32[NT*NT*E], 10 Bm f32[NC*NC*E],
// 11 Q f32[NC*NC*E].  Output: scalar f32.

namespace {
constexpr int NTY = 50;
constexpr int NCA = 20;
constexpr int EMB = 64;
constexpr int BSZ = 4;
constexpr int SEQ = 256;
constexpr float NL2E = -1.4426950408889634f;  // -log2(e)

// main grid: heavy blocks first
constexpr int HT_BLKS = BSZ * NTY;                        // 200 (full-256 loops)
constexpr int HC_BLKS = BSZ;                              // 4
constexpr int EV_BLKS = BSZ * SEQ;                        // 1024
constexpr int MAIN_BLKS = HT_BLKS + HC_BLKS + EV_BLKS;    // 1228

// prep grid
constexpr int TT_BLKS = (NTY * NTY) / 4;                  // 625
constexpr int TC_BLKS = (NCA * NCA) / 4;                  // 100
constexpr int FB_BLKS = (NTY * NCA + 7) / 8;              // 125 (warp per dot)
constexpr int BA_BLKS = (NTY + 7) / 8;                    // 7   (warp per row)
constexpr int PREP_BLKS = TT_BLKS + TC_BLKS + FB_BLKS + BA_BLKS + 1;  // 858
}

// Tables, [target][source][e] so each consumer block hits a contiguous slice.
__device__ float2 g_TT[NTY * NTY * EMB];   // {f[t]A[k,t]f[k], NL2E*f[t]P[k,t]f[k]}
__device__ float2 g_TC[NCA * NCA * EMB];   // {g[c2]Bm[c1,c2]g[c1], NL2E*g[c2]Q[c1,c2]g[c1]}
__device__ float g_BA[NTY];                // sum_e f*a
__device__ float g_SP[NTY];                // sum_e softplus(f*a)
__device__ float g_FB[NTY * NCA];          // sum_e f[t]*b[c]
__device__ float g_Fsum[EMB];              // sum_t f[t,e]
__device__ float g_SFB[NCA];               // sum_t FB[t,c]
__device__ float g_Sba, g_I0;
__device__ float g_part[MAIN_BLKS];
__device__ unsigned g_done;                // zero-init; finalizer resets (replay-safe)

struct alignas(16) Ent { float t; int ko; int co; int pad; };

__device__ __forceinline__ float fast_exp2(float x) {
    float r;
    asm("ex2.approx.ftz.f32 %0, %1;" : "=f"(r) : "f"(x));
    return r;
}

__device__ __forceinline__ float softplusf(float x) {
    return fmaxf(x, 0.f) + log1pf(expf(-fabsf(x)));
}

// T may arrive as int32 (value 128) or float32 bits; disambiguate.
__device__ __forceinline__ float readT(const void* p) {
    int v = *(const int*)p;
    return (v > 0 && v < (1 << 24)) ? (float)v : __int_as_float(v);
}

__device__ __forceinline__ float warp_reduce(float v) {
    #pragma unroll
    for (int o = 16; o; o >>= 1) v += __shfl_down_sync(0xffffffffu, v, o);
    return v;
}

__device__ __forceinline__ float block_reduce_256(float v, float* sred) {
    v = warp_reduce(v);
    int tid = threadIdx.x;
    if ((tid & 31) == 0) sred[tid >> 5] = v;
    __syncthreads();
    float r = 0.f;
    if (tid == 0) {
        #pragma unroll
        for (int w = 0; w < 8; w++) r += sred[w];
    }
    return r;
}

// ======================= prep: tables + scalars, all parallel ================
__global__ void __launch_bounds__(256) k_prep(
    const float* __restrict__ f, const float* __restrict__ g,
    const float* __restrict__ a, const float* __restrict__ b,
    const float* __restrict__ A, const float* __restrict__ P,
    const float* __restrict__ Bm, const float* __restrict__ Q) {
    int bid = blockIdx.x;
    int tid = threadIdx.x;

    if (bid < TT_BLKS) {
        int p = bid * 4 + (tid >> 6);           // p = t*NTY + k (write index)
        int e = tid & (EMB - 1);
        int t = p / NTY, k = p - t * NTY;
        int rd = (k * NTY + t) * EMB + e;       // A/P stored [k][t][e]
        float w = f[t * EMB + e] * f[k * EMB + e];
        float2 v;
        v.x = w * __ldg(A + rd);
        v.y = NL2E * w * __ldg(P + rd);
        g_TT[p * EMB + e] = v;
        return;
    }
    bid -= TT_BLKS;
    if (bid < TC_BLKS) {
        int p = bid * 4 + (tid >> 6);           // p = c2*NCA + c1 (write index)
        int e = tid & (EMB - 1);
        int c2 = p / NCA, c1 = p - c2 * NCA;
        int rd = (c1 * NCA + c2) * EMB + e;     // Bm/Q stored [c1][c2][e]
        float w = g[c2 * EMB + e] * g[c1 * EMB + e];
        float2 v;
        v.x = w * __ldg(Bm + rd);
        v.y = NL2E * w * __ldg(Q + rd);
        g_TC[p * EMB + e] = v;
        return;
    }
    bid -= TC_BLKS;
    if (bid < FB_BLKS) {
        int w = tid >> 5, lane = tid & 31;
        int idx = bid * 8 + w;
        if (idx < NTY * NCA) {
            int t = idx / NCA, c = idx - t * NCA;
            float s = f[t * EMB + lane] * b[c * EMB + lane]
                    + f[t * EMB + lane + 32] * b[c * EMB + lane + 32];
            s = warp_reduce(s);
            if (lane == 0) g_FB[idx] = s;
        }
        return;
    }
    bid -= FB_BLKS;
    if (bid < BA_BLKS) {
        int w = tid >> 5, lane = tid & 31;
        int t = bid * 8 + w;
        if (t < NTY) {
            float x0 = f[t * EMB + lane] * a[t * EMB + lane];
            float x1 = f[t * EMB + lane + 32] * a[t * EMB + lane + 32];
            float ba = warp_reduce(x0 + x1);
            float sp = warp_reduce(softplusf(x0) + softplusf(x1));
            if (lane == 0) { g_BA[t] = ba; g_SP[t] = sp; }
        }
        return;
    }
    // ---- final scalar block: Fsum, SFB, Sba, I0 ----
    __shared__ float fs_sh[EMB];
    __shared__ float sred1[8];
    __shared__ float sred2[8];
    if (tid < EMB) {
        float s = 0.f;
        #pragma unroll
        for (int t = 0; t < NTY; t++) s += f[t * EMB + tid];
        g_Fsum[tid] = s;
        fs_sh[tid] = s;
    }
    float sba = 0.f, i0 = 0.f;
    for (int idx = tid; idx < NTY * EMB; idx += 256) {
        float x = f[idx] * a[idx];
        sba += x;
        i0 += softplusf(x);
    }
    sba = warp_reduce(sba);
    i0 = warp_reduce(i0);
    if ((tid & 31) == 0) { sred1[tid >> 5] = sba; sred2[tid >> 5] = i0; }
    __syncthreads();
    if (tid == 0) {
        float s = 0.f, s2 = 0.f;
        #pragma unroll
        for (int w = 0; w < 8; w++) { s += sred1[w]; s2 += sred2[w]; }
        g_Sba = s;
        g_I0 = s2;
    }
    // SFB[c] = sum_e Fsum[e]*b[c,e] (warp per c, strided)
    {
        int w = tid >> 5, lane = tid & 31;
        for (int c = w; c < NCA; c += 8) {
            float s = fs_sh[lane] * b[c * EMB + lane]
                    + fs_sh[lane + 32] * b[c * EMB + lane + 32];
            s = warp_reduce(s);
            if (lane == 0) g_SFB[c] = s;
        }
    }
}

// ======================= main: events + horizon + finalizer =================
__global__ void __launch_bounds__(256) k_main(
    const float* __restrict__ times, const int* __restrict__ types,
    const int* __restrict__ cats, const void* __restrict__ Tp,
    const float* __restrict__ f, float* __restrict__ out) {
    int bid = blockIdx.x;
    int tid = threadIdx.x;
    __shared__ Ent sh[SEQ];
    __shared__ float sred[8];
    __shared__ double dred[8];
    __shared__ int sh_last;

    int e = tid & (EMB - 1);
    int ch = tid >> 6;  // 0..3
    float partial = 0.f;

    if (bid < HT_BLKS) {
        // ---- horizon type channel: (b, t) ----
        int bb = bid / NTY;
        int t = bid - bb * NTY;
        float Tf = readT(Tp);
        const float* ts = times + bb * SEQ;
        const int* ty = types + bb * SEQ;
        for (int s = tid; s < SEQ; s += 256) {
            Ent en; en.t = ts[s]; en.ko = ty[s] * EMB; en.co = 0; en.pad = 0;
            sh[s] = en;
        }
        __syncthreads();
        const float2* __restrict__ ttb = g_TT + (size_t)t * (NTY * EMB) + e;
        float a0 = 0.f, a1 = 0.f, a2 = 0.f, a3 = 0.f;
        #pragma unroll 2
        for (int s = ch; s < SEQ; s += 16) {
            Ent e0 = sh[s], e1 = sh[s + 4], e2 = sh[s + 8], e3 = sh[s + 12];
            float2 w0 = __ldg(ttb + e0.ko);
            float2 w1 = __ldg(ttb + e1.ko);
            float2 w2 = __ldg(ttb + e2.ko);
            float2 w3 = __ldg(ttb + e3.ko);
            a0 = fmaf(w0.x, fast_exp2(w0.y * (Tf - e0.t)), a0);
            a1 = fmaf(w1.x, fast_exp2(w1.y * (Tf - e1.t)), a1);
            a2 = fmaf(w2.x, fast_exp2(w2.y * (Tf - e2.t)), a2);
            a3 = fmaf(w3.x, fast_exp2(w3.y * (Tf - e3.t)), a3);
        }
        float total = block_reduce_256((a0 + a1) + (a2 + a3), sred);
        if (tid == 0) partial = total * (Tf - sh[SEQ - 1].t);
    } else if (bid < HT_BLKS + HC_BLKS) {
        // ---- horizon category channel: b ----
        int bb = bid - HT_BLKS;
        float Tf = readT(Tp);
        const float* ts = times + bb * SEQ;
        const int* ct = cats + bb * SEQ;
        for (int s = tid; s < SEQ; s += 256) {
            Ent en; en.t = ts[s]; en.co = ct[s] * EMB; en.ko = 0; en.pad = 0;
            sh[s] = en;
        }
        __syncthreads();
        int lcL = ct[SEQ - 1];
        const float2* __restrict__ tcb = g_TC + (size_t)lcL * (NCA * EMB) + e;
        float a0 = 0.f, a1 = 0.f, a2 = 0.f, a3 = 0.f;
        #pragma unroll 2
        for (int s = ch; s < SEQ; s += 16) {
            Ent e0 = sh[s], e1 = sh[s + 4], e2 = sh[s + 8], e3 = sh[s + 12];
            float2 w0 = __ldg(tcb + e0.co);
            float2 w1 = __ldg(tcb + e1.co);
            float2 w2 = __ldg(tcb + e2.co);
            float2 w3 = __ldg(tcb + e3.co);
            a0 = fmaf(w0.x, fast_exp2(w0.y * (Tf - e0.t)), a0);
            a1 = fmaf(w1.x, fast_exp2(w1.y * (Tf - e1.t)), a1);
            a2 = fmaf(w2.x, fast_exp2(w2.y * (Tf - e2.t)), a2);
            a3 = fmaf(w3.x, fast_exp2(w3.y * (Tf - e3.t)), a3);
        }
        float acc = ((a0 + a1) + (a2 + a3)) * g_Fsum[e];
        float total = block_reduce_256(acc, sred);
        if (tid == 0) partial = total * (Tf - sh[SEQ - 1].t);
    } else {
        // ---- per-event log-likelihood (global descending-i order) ----
        int local = bid - HT_BLKS - HC_BLKS;
        int i = (SEQ - 1) - (local >> 2);
        int bb = local & 3;
        const float* ts = times + bb * SEQ;
        const int* ty = types + bb * SEQ;
        const int* ct = cats + bb * SEQ;
        int ti = ty[i];
        float t_i = ts[i];

        if (i == 0) {
            if (tid == 0 && t_i >= 0.f) {
                float lam = g_SP[ti];
                partial = -(logf(lam + 1e-16f) + lam);
            }
        } else {
            for (int s = tid; s < i; s += 256) {
                Ent en;
                en.t = ts[s];
                en.ko = ty[s] * EMB;
                en.co = ct[s] * EMB;
                en.pad = 0;
                sh[s] = en;
            }
            __syncthreads();

            int lc = ct[i - 1];
            const float2* __restrict__ ttb = g_TT + (size_t)ti * (NTY * EMB) + e;
            const float2* __restrict__ tcb = g_TC + (size_t)lc * (NCA * EMB) + e;
            float aT0 = 0.f, aT1 = 0.f, aT2 = 0.f, aT3 = 0.f;
            float aC0 = 0.f, aC1 = 0.f, aC2 = 0.f, aC3 = 0.f;
            int s = ch;
            for (; s + 12 < i; s += 16) {
                Ent e0 = sh[s], e1 = sh[s + 4], e2 = sh[s + 8], e3 = sh[s + 12];
                float2 t0 = __ldg(ttb + e0.ko);
                float2 c0 = __ldg(tcb + e0.co);
                float2 t1 = __ldg(ttb + e1.ko);
                float2 c1 = __ldg(tcb + e1.co);
                float2 t2 = __ldg(ttb + e2.ko);
                float2 c2 = __ldg(tcb + e2.co);
                float2 t3 = __ldg(ttb + e3.ko);
                float2 c3 = __ldg(tcb + e3.co);
                float d0 = t_i - e0.t, d1 = t_i - e1.t;
                float d2 = t_i - e2.t, d3 = t_i - e3.t;
                aT0 = fmaf(t0.x, fast_exp2(t0.y * d0), aT0);
                aC0 = fmaf(c0.x, fast_exp2(c0.y * d0), aC0);
                aT1 = fmaf(t1.x, fast_exp2(t1.y * d1), aT1);
                aC1 = fmaf(c1.x, fast_exp2(c1.y * d1), aC1);
                aT2 = fmaf(t2.x, fast_exp2(t2.y * d2), aT2);
                aC2 = fmaf(c2.x, fast_exp2(c2.y * d2), aC2);
                aT3 = fmaf(t3.x, fast_exp2(t3.y * d3), aT3);
                aC3 = fmaf(c3.x, fast_exp2(c3.y * d3), aC3);
            }
            for (; s < i; s += 4) {
                Ent e0 = sh[s];
                float2 t0 = __ldg(ttb + e0.ko);
                float2 c0 = __ldg(tcb + e0.co);
                float d0 = t_i - e0.t;
                aT0 = fmaf(t0.x, fast_exp2(t0.y * d0), aT0);
                aC0 = fmaf(c0.x, fast_exp2(c0.y * d0), aC0);
            }
            float fe = __ldg(f + ti * EMB + e);
            float acc = ((aT0 + aT1) + (aT2 + aT3))
                      + fe * ((aC0 + aC1) + (aC2 + aC3));
            float total = block_reduce_256(acc, sred);
            if (tid == 0 && t_i >= 0.f) {
                float lam = g_BA[ti] + g_FB[ti * NCA + lc] + total;
                partial = -(logf(lam + 1e-16f) + lam);
            }
        }
    }

    // ---- publish partial + grid-completion finalizer ----
    if (tid == 0) {
        g_part[bid] = partial;
        __threadfence();
        unsigned n = atomicAdd(&g_done, 1u);
        sh_last = (n == (unsigned)(MAIN_BLKS - 1)) ? 1 : 0;
        if (sh_last) __threadfence();
    }
    __syncthreads();
    if (sh_last) {
        double v = 0.0;
        for (int idx = tid; idx < MAIN_BLKS; idx += 256) v += (double)g_part[idx];
        #pragma unroll
        for (int o = 16; o; o >>= 1) v += __shfl_down_sync(0xffffffffu, v, o);
        if ((tid & 31) == 0) dred[tid >> 5] = v;
        __syncthreads();
        if (tid == 0) {
            double r = 0.0;
            #pragma unroll
            for (int w = 0; w < 8; w++) r += dred[w];
            float Tf = readT(Tp);
            for (int b2 = 0; b2 < BSZ; b2++) {
                int lcL = cats[b2 * SEQ + SEQ - 1];
                float tlast = times[b2 * SEQ + SEQ - 1];
                float t0 = times[b2 * SEQ];
                r += (double)((g_Sba + g_SFB[lcL]) * (Tf - tlast) + g_I0 * t0);
            }
            out[0] = (float)r;
            g_done = 0u;  // reset for next replay
        }
    }
}

extern "C" void kernel_launch(void* const* d_in, const int* in_sizes, int n_in,
                              void* d_out, int out_size) {
    const float* times = (const float*)d_in[0];
    const int* types = (const int*)d_in[1];
    const int* cats = (const int*)d_in[2];
    const void* Tp = d_in[3];
    const float* type_emb = (const float*)d_in[4];
    const float* cat_emb = (const float*)d_in[5];
    const float* a = (const float*)d_in[6];
    const float* b = (const float*)d_in[7];
    const float* A = (const float*)d_in[8];
    const float* P = (const float*)d_in[9];
    const float* Bm = (const float*)d_in[10];
    const float* Q = (const float*)d_in[11];
    float* out = (float*)d_out;

    k_prep<<<PREP_BLKS, 256>>>(type_emb, cat_emb, a, b, A, P, Bm, Q);
    k_main<<<MAIN_BLKS, 256>>>(times, types, cats, Tp, type_emb, out);
}

// round 5
// speedup vs baseline: 2.5670x; 1.0115x over previous
#include <cuda_runtime.h>

// CEHawkesProcess — Hawkes NLL. 2 launches: vectorized prep + balanced single-wave main.
// Inputs (metadata order):
// 0 event_times f32[B*L], 1 event_types i32[B*L], 2 event_categories i32[B*L],
// 3 T (scalar), 4 type_emb f32[NT*E], 5 cat_emb f32[NC*E], 6 a f32[NT*E],
// 7 b f32[NC*E], 8 A f32[NT*NT*E], 9 P f32[NT*NT*E], 10 Bm f32[NC*NC*E],
// 11 Q f32[NC*NC*E].  Output: scalar f32.

namespace {
constexpr int NTY = 50;
constexpr int NCA = 20;
constexpr int EMB = 64;
constexpr int BSZ = 4;
constexpr int SEQ = 256;
constexpr float NL2E = -1.4426950408889634f;  // -log2(e)

// main grid: paired work units, ~equal cost per block (single wave)
constexpr int EVP_BLKS = BSZ * (SEQ / 2);                 // 512  (event pairs i, 255-i)
constexpr int HTP_BLKS = BSZ * (NTY / 2);                 // 100  (horizon type pairs t, t+25)
constexpr int HC_BLKS = BSZ;                              // 4
constexpr int MAIN_BLKS = EVP_BLKS + HTP_BLKS + HC_BLKS;  // 616

// prep grid (vectorized: 16 table rows / block, float4)
constexpr int TT_BLKS = (NTY * NTY + 15) / 16;            // 157
constexpr int TC_BLKS = (NCA * NCA + 15) / 16;            // 25
constexpr int FB_BLKS = (NTY * NCA + 7) / 8;              // 125
constexpr int BA_BLKS = (NTY + 7) / 8;                    // 7
constexpr int PREP_BLKS = TT_BLKS + TC_BLKS + FB_BLKS + BA_BLKS + 1;  // 315
}

// Tables, [target][source][e]: consumer block reads a contiguous slice.
__device__ float2 g_TT[NTY * NTY * EMB];   // {f[t]A[k,t]f[k], NL2E*f[t]P[k,t]f[k]}
__device__ float2 g_TC[NCA * NCA * EMB];   // {g[c2]Bm[c1,c2]g[c1], NL2E*g[c2]Q[c1,c2]g[c1]}
__device__ float g_BA[NTY];                // sum_e f*a
__device__ float g_SP[NTY];                // sum_e softplus(f*a)
__device__ float g_FB[NTY * NCA];          // sum_e f[t]*b[c]
__device__ float g_Fsum[EMB];              // sum_t f[t,e]
__device__ float g_SFB[NCA];               // sum_t FB[t,c]
__device__ float g_Sba, g_I0;
__device__ float g_part[MAIN_BLKS];
__device__ unsigned g_done;                // zero-init; finalizer resets (replay-safe)

struct alignas(16) Ent { float t; int ko; int co; int pad; };

__device__ __forceinline__ float fast_exp2(float x) {
    float r;
    asm("ex2.approx.ftz.f32 %0, %1;" : "=f"(r) : "f"(x));
    return r;
}

__device__ __forceinline__ float softplusf(float x) {
    return fmaxf(x, 0.f) + log1pf(expf(-fabsf(x)));
}

// T may arrive as int32 (value 128) or float32 bits; disambiguate.
__device__ __forceinline__ float readT(const void* p) {
    int v = *(const int*)p;
    return (v > 0 && v < (1 << 24)) ? (float)v : __int_as_float(v);
}

__device__ __forceinline__ float warp_reduce(float v) {
    #pragma unroll
    for (int o = 16; o; o >>= 1) v += __shfl_down_sync(0xffffffffu, v, o);
    return v;
}

// sred must be distinct per call when reductions are back-to-back (no trailing sync).
__device__ __forceinline__ float block_reduce_256(float v, float* sred) {
    v = warp_reduce(v);
    int tid = threadIdx.x;
    if ((tid & 31) == 0) sred[tid >> 5] = v;
    __syncthreads();
    float r = 0.f;
    if (tid == 0) {
        #pragma unroll
        for (int w = 0; w < 8; w++) r += sred[w];
    }
    return r;
}

// ======================= prep: tables + scalars, all parallel ================
__global__ void __launch_bounds__(256) k_prep(
    const float* __restrict__ f, const float* __restrict__ g,
    const float* __restrict__ a, const float* __restrict__ b,
    const float* __restrict__ A, const float* __restrict__ P,
    const float* __restrict__ Bm, const float* __restrict__ Q) {
    int bid = blockIdx.x;
    int tid = threadIdx.x;

    if (bid < TT_BLKS) {
        int p = bid * 16 + (tid >> 4);          // p = t*NTY + k (write row)
        if (p < NTY * NTY) {
            int e = (tid & 15) << 2;
            int t = p / NTY, k = p - t * NTY;
            int rd = (k * NTY + t) * EMB + e;   // A/P stored [k][t][e]
            float4 Av = *(const float4*)(A + rd);
            float4 Pv = *(const float4*)(P + rd);
            float4 ft = *(const float4*)(f + t * EMB + e);
            float4 fk = *(const float4*)(f + k * EMB + e);
            float w0 = ft.x * fk.x, w1 = ft.y * fk.y;
            float w2 = ft.z * fk.z, w3 = ft.w * fk.w;
            float4* dst = (float4*)(g_TT + p * EMB + e);
            dst[0] = make_float4(w0 * Av.x, NL2E * w0 * Pv.x, w1 * Av.y, NL2E * w1 * Pv.y);
            dst[1] = make_float4(w2 * Av.z, NL2E * w2 * Pv.z, w3 * Av.w, NL2E * w3 * Pv.w);
        }
        return;
    }
    bid -= TT_BLKS;
    if (bid < TC_BLKS) {
        int p = bid * 16 + (tid >> 4);          // p = c2*NCA + c1 (write row)
        if (p < NCA * NCA) {
            int e = (tid & 15) << 2;
            int c2 = p / NCA, c1 = p - c2 * NCA;
            int rd = (c1 * NCA + c2) * EMB + e; // Bm/Q stored [c1][c2][e]
            float4 Bv = *(const float4*)(Bm + rd);
            float4 Qv = *(const float4*)(Q + rd);
            float4 g2 = *(const float4*)(g + c2 * EMB + e);
            float4 g1 = *(const float4*)(g + c1 * EMB + e);
            float w0 = g2.x * g1.x, w1 = g2.y * g1.y;
            float w2 = g2.z * g1.z, w3 = g2.w * g1.w;
            float4* dst = (float4*)(g_TC + p * EMB + e);
            dst[0] = make_float4(w0 * Bv.x, NL2E * w0 * Qv.x, w1 * Bv.y, NL2E * w1 * Qv.y);
            dst[1] = make_float4(w2 * Bv.z, NL2E * w2 * Qv.z, w3 * Bv.w, NL2E * w3 * Qv.w);
        }
        return;
    }
    bid -= TC_BLKS;
    if (bid < FB_BLKS) {
        int w = tid >> 5, lane = tid & 31;
        int idx = bid * 8 + w;
        if (idx < NTY * NCA) {
            int t = idx / NCA, c = idx - t * NCA;
            float s = f[t * EMB + lane] * b[c * EMB + lane]
                    + f[t * EMB + lane + 32] * b[c * EMB + lane + 32];
            s = warp_reduce(s);
            if (lane == 0) g_FB[idx] = s;
        }
        return;
    }
    bid -= FB_BLKS;
    if (bid < BA_BLKS) {
        int w = tid >> 5, lane = tid & 31;
        int t = bid * 8 + w;
        if (t < NTY) {
            float x0 = f[t * EMB + lane] * a[t * EMB + lane];
            float x1 = f[t * EMB + lane + 32] * a[t * EMB + lane + 32];
            float ba = warp_reduce(x0 + x1);
            float sp = warp_reduce(softplusf(x0) + softplusf(x1));
            if (lane == 0) { g_BA[t] = ba; g_SP[t] = sp; }
        }
        return;
    }
    // ---- final scalar block: Fsum, SFB, Sba, I0 ----
    __shared__ float fs_sh[EMB];
    __shared__ float sred1[8];
    __shared__ float sred2[8];
    if (tid < EMB) {
        float s = 0.f;
        #pragma unroll
        for (int t = 0; t < NTY; t++) s += f[t * EMB + tid];
        g_Fsum[tid] = s;
        fs_sh[tid] = s;
    }
    float sba = 0.f, i0 = 0.f;
    for (int idx = tid; idx < NTY * EMB; idx += 256) {
        float x = f[idx] * a[idx];
        sba += x;
        i0 += softplusf(x);
    }
    sba = warp_reduce(sba);
    i0 = warp_reduce(i0);
    if ((tid & 31) == 0) { sred1[tid >> 5] = sba; sred2[tid >> 5] = i0; }
    __syncthreads();
    if (tid == 0) {
        float s = 0.f, s2 = 0.f;
        #pragma unroll
        for (int w = 0; w < 8; w++) { s += sred1[w]; s2 += sred2[w]; }
        g_Sba = s;
        g_I0 = s2;
    }
    {
        int w = tid >> 5, lane = tid & 31;
        for (int c = w; c < NCA; c += 8) {
            float s = fs_sh[lane] * b[c * EMB + lane]
                    + fs_sh[lane + 32] * b[c * EMB + lane + 32];
            s = warp_reduce(s);
            if (lane == 0) g_SFB[c] = s;
        }
    }
}

// ======================= main: balanced paired blocks ========================
__global__ void __launch_bounds__(256, 5) k_main(
    const float* __restrict__ times, const int* __restrict__ types,
    const int* __restrict__ cats, const void* __restrict__ Tp,
    float* __restrict__ out) {
    int bid = blockIdx.x;
    int tid = threadIdx.x;
    __shared__ Ent sh[SEQ];
    __shared__ float sredA[8];
    __shared__ float sredB[8];
    __shared__ double dred[8];
    __shared__ int sh_last;

    int e = tid & (EMB - 1);
    int ch = tid >> 6;  // 0..3
    float partial = 0.f;

    if (bid < EVP_BLKS) {
        // ---- event pair (i_hi = 255-p, i_lo = p): uniform 510 work units ----
        int bb = bid & 3;
        int p = bid >> 2;                   // 0..127
        int i_hi = (SEQ - 1) - p;           // 128..255
        int i_lo = p;                       // 0..127
        const float* ts = times + bb * SEQ;
        const int* ty = types + bb * SEQ;
        const int* ct = cats + bb * SEQ;

        for (int s = tid; s < i_hi; s += 256) {
            Ent en;
            en.t = ts[s];
            en.ko = ty[s] * EMB;
            en.co = ct[s] * EMB;
            en.pad = 0;
            sh[s] = en;
        }
        __syncthreads();

        // ---- pass A: event i_hi ----
        {
            int i = i_hi;
            int ti = ty[i];
            float t_i = ts[i];
            int lc = sh[i - 1].co / EMB;
            const float2* __restrict__ ttb = g_TT + (size_t)ti * (NTY * EMB) + e;
            const float2* __restrict__ tcb = g_TC + (size_t)lc * (NCA * EMB) + e;
            float aT0 = 0.f, aT1 = 0.f, aC0 = 0.f, aC1 = 0.f;
            int s = ch;
            for (; s + 4 < i; s += 8) {
                Ent e0 = sh[s], e1 = sh[s + 4];
                float2 t0 = __ldg(ttb + e0.ko);
                float2 c0 = __ldg(tcb + e0.co);
                float2 t1 = __ldg(ttb + e1.ko);
                float2 c1 = __ldg(tcb + e1.co);
                float d0 = t_i - e0.t, d1 = t_i - e1.t;
                aT0 = fmaf(t0.x, fast_exp2(t0.y * d0), aT0);
                aC0 = fmaf(c0.x, fast_exp2(c0.y * d0), aC0);
                aT1 = fmaf(t1.x, fast_exp2(t1.y * d1), aT1);
                aC1 = fmaf(c1.x, fast_exp2(c1.y * d1), aC1);
            }
            if (s < i) {
                Ent e0 = sh[s];
                float2 t0 = __ldg(ttb + e0.ko);
                float2 c0 = __ldg(tcb + e0.co);
                float d0 = t_i - e0.t;
                aT0 = fmaf(t0.x, fast_exp2(t0.y * d0), aT0);
                aC0 = fmaf(c0.x, fast_exp2(c0.y * d0), aC0);
            }
            float fe = g_Fsum[e];  // placeholder avoided; need f[ti,e]:
            // f[ti,e] = sqrt of table? No — read from type_emb via g_TT? Use direct:
            // (we pass f through times pointer? no) -> use __ldg on global f pointer below.
            (void)fe;
            // defer fe multiply: use constant memory trick instead (see below)
            float accT = aT0 + aT1, accC = aC0 + aC1;
            // fe lookup via g_FE table (stored in g_Fsum? no). We store f in g_FEmb:
            extern __device__ float g_FEmb[];  // fwd decl resolved below
            float fev = __ldg(&g_FEmb[ti * EMB + e]);
            float acc = accT + fev * accC;
            float total = block_reduce_256(acc, sredA);
            if (tid == 0 && t_i >= 0.f) {
                float lam = g_BA[ti] + g_FB[ti * NCA + lc] + total;
                partial = -(logf(lam + 1e-16f) + lam);
            }
        }
        // ---- pass B: event i_lo ----
        if (i_lo == 0) {
            if (tid == 0) {
                float t0v = ts[0];
                if (t0v >= 0.f) {
                    float lam = g_SP[ty[0]];
                    partial += -(logf(lam + 1e-16f) + lam);
                }
            }
        } else {
            int i = i_lo;
            int ti = ty[i];
            float t_i = ts[i];
            int lc = sh[i - 1].co / EMB;
            const float2* __restrict__ ttb = g_TT + (size_t)ti * (NTY * EMB) + e;
            const float2* __restrict__ tcb = g_TC + (size_t)lc * (NCA * EMB) + e;
            float aT0 = 0.f, aT1 = 0.f, aC0 = 0.f, aC1 = 0.f;
            int s = ch;
            for (; s + 4 < i; s += 8) {
                Ent e0 = sh[s], e1 = sh[s + 4];
                float2 t0 = __ldg(ttb + e0.ko);
                float2 c0 = __ldg(tcb + e0.co);
                float2 t1 = __ldg(ttb + e1.ko);
                float2 c1 = __ldg(tcb + e1.co);
                float d0 = t_i - e0.t, d1 = t_i - e1.t;
                aT0 = fmaf(t0.x, fast_exp2(t0.y * d0), aT0);
                aC0 = fmaf(c0.x, fast_exp2(c0.y * d0), aC0);
                aT1 = fmaf(t1.x, fast_exp2(t1.y * d1), aT1);
                aC1 = fmaf(c1.x, fast_exp2(c1.y * d1), aC1);
            }
            if (s < i) {
                Ent e0 = sh[s];
                float2 t0 = __ldg(ttb + e0.ko);
                float2 c0 = __ldg(tcb + e0.co);
                float d0 = t_i - e0.t;
                aT0 = fmaf(t0.x, fast_exp2(t0.y * d0), aT0);
                aC0 = fmaf(c0.x, fast_exp2(c0.y * d0), aC0);
            }
            extern __device__ float g_FEmb[];
            float fev = __ldg(&g_FEmb[ti * EMB + e]);
            float acc = (aT0 + aT1) + fev * (aC0 + aC1);
            float total = block_reduce_256(acc, sredB);
            if (tid == 0 && t_i >= 0.f) {
                float lam = g_BA[ti] + g_FB[ti * NCA + lc] + total;
                partial += -(logf(lam + 1e-16f) + lam);
            }
        }
    } else if (bid < EVP_BLKS + HTP_BLKS) {
        // ---- horizon type pair: (b, t) and (b, t+25) ----
        int idx0 = bid - EVP_BLKS;
        int bb = idx0 / (NTY / 2);
        int tp = idx0 - bb * (NTY / 2);     // 0..24
        float Tf = readT(Tp);
        const float* ts = times + bb * SEQ;
        const int* ty = types + bb * SEQ;
        for (int s = tid; s < SEQ; s += 256) {
            Ent en; en.t = ts[s]; en.ko = ty[s] * EMB; en.co = 0; en.pad = 0;
            sh[s] = en;
        }
        __syncthreads();
        float tgap = Tf - sh[SEQ - 1].t;
        float* sr = sredA;
        #pragma unroll
        for (int half = 0; half < 2; half++) {
            int t = tp + half * (NTY / 2);
            const float2* __restrict__ ttb = g_TT + (size_t)t * (NTY * EMB) + e;
            float a0 = 0.f, a1 = 0.f, a2 = 0.f, a3 = 0.f;
            #pragma unroll 2
            for (int s = ch; s < SEQ; s += 16) {
                Ent e0 = sh[s], e1 = sh[s + 4], e2 = sh[s + 8], e3 = sh[s + 12];
                float2 w0 = __ldg(ttb + e0.ko);
                float2 w1 = __ldg(ttb + e1.ko);
                float2 w2 = __ldg(ttb + e2.ko);
                float2 w3 = __ldg(ttb + e3.ko);
                a0 = fmaf(w0.x, fast_exp2(w0.y * (Tf - e0.t)), a0);
                a1 = fmaf(w1.x, fast_exp2(w1.y * (Tf - e1.t)), a1);
                a2 = fmaf(w2.x, fast_exp2(w2.y * (Tf - e2.t)), a2);
                a3 = fmaf(w3.x, fast_exp2(w3.y * (Tf - e3.t)), a3);
            }
            float total = block_reduce_256((a0 + a1) + (a2 + a3), sr);
            if (tid == 0) partial += total * tgap;
            sr = sredB;
        }
    } else {
        // ---- horizon category channel: b ----
        int bb = bid - EVP_BLKS - HTP_BLKS;
        float Tf = readT(Tp);
        const float* ts = times + bb * SEQ;
        const int* ct = cats + bb * SEQ;
        for (int s = tid; s < SEQ; s += 256) {
            Ent en; en.t = ts[s]; en.co = ct[s] * EMB; en.ko = 0; en.pad = 0;
            sh[s] = en;
        }
        __syncthreads();
        int lcL = ct[SEQ - 1];
        const float2* __restrict__ tcb = g_TC + (size_t)lcL * (NCA * EMB) + e;
        float a0 = 0.f, a1 = 0.f, a2 = 0.f, a3 = 0.f;
        #pragma unroll 2
        for (int s = ch; s < SEQ; s += 16) {
            Ent e0 = sh[s], e1 = sh[s + 4], e2 = sh[s + 8], e3 = sh[s + 12];
            float2 w0 = __ldg(tcb + e0.co);
            float2 w1 = __ldg(tcb + e1.co);
            float2 w2 = __ldg(tcb + e2.co);
            float2 w3 = __ldg(tcb + e3.co);
            a0 = fmaf(w0.x, fast_exp2(w0.y * (Tf - e0.t)), a0);
            a1 = fmaf(w1.x, fast_exp2(w1.y * (Tf - e1.t)), a1);
            a2 = fmaf(w2.x, fast_exp2(w2.y * (Tf - e2.t)), a2);
            a3 = fmaf(w3.x, fast_exp2(w3.y * (Tf - e3.t)), a3);
        }
        float acc = ((a0 + a1) + (a2 + a3)) * g_Fsum[e];
        float total = block_reduce_256(acc, sredA);
        if (tid == 0) partial = total * (Tf - sh[SEQ - 1].t);
    }

    // ---- publish partial + grid-completion finalizer ----
    if (tid == 0) {
        g_part[bid] = partial;
        __threadfence();
        unsigned n = atomicAdd(&g_done, 1u);
        sh_last = (n == (unsigned)(MAIN_BLKS - 1)) ? 1 : 0;
        if (sh_last) __threadfence();
    }
    __syncthreads();
    if (sh_last) {
        double v = 0.0;
        for (int idx = tid; idx < MAIN_BLKS; idx += 256) v += (double)g_part[idx];
        #pragma unroll
        for (int o = 16; o; o >>= 1) v += __shfl_down_sync(0xffffffffu, v, o);
        if ((tid & 31) == 0) dred[tid >> 5] = v;
        __syncthreads();
        if (tid == 0) {
            double r = 0.0;
            #pragma unroll
            for (int w = 0; w < 8; w++) r += dred[w];
            float Tf = readT(Tp);
            for (int b2 = 0; b2 < BSZ; b2++) {
                int lcL = cats[b2 * SEQ + SEQ - 1];
                float tlast = times[b2 * SEQ + SEQ - 1];
                float t0 = times[b2 * SEQ];
                r += (double)((g_Sba + g_SFB[lcL]) * (Tf - tlast) + g_I0 * t0);
            }
            out[0] = (float)r;
            g_done = 0u;  // reset for next replay
        }
    }
}

// f embedding copy (so k_main needs no extra pointer args in hot path)
__device__ float g_FEmb[NTY * EMB];

__global__ void k_copyf(const float* __restrict__ f) {
    int i = blockIdx.x * 256 + threadIdx.x;
    if (i < NTY * EMB) g_FEmb[i] = f[i];
}

extern "C" void kernel_launch(void* const* d_in, const int* in_sizes, int n_in,
                              void* d_out, int out_size) {
    const float* times = (const float*)d_in[0];
    const int* types = (const int*)d_in[1];
    const int* cats = (const int*)d_in[2];
    const void* Tp = d_in[3];
    const float* type_emb = (const float*)d_in[4];
    const float* cat_emb = (const float*)d_in[5];
    const float* a = (const float*)d_in[6];
    const float* b = (const float*)d_in[7];
    const float* A = (const float*)d_in[8];
    const float* P = (const float*)d_in[9];
    const float* Bm = (const float*)d_in[10];
    const float* Q = (const float*)d_in[11];
    float* out = (float*)d_out;

    k_copyf<<<(NTY * EMB + 255) / 256, 256>>>(type_emb);
    k_prep<<<PREP_BLKS, 256>>>(type_emb, cat_emb, a, b, A, P, Bm, Q);
    k_main<<<MAIN_BLKS, 256>>>(times, types, cats, Tp, out);
}